// round 17
// baseline (speedup 1.0000x reference)
#include <cuda_runtime.h>
#include <cstdint>

// RSNALoss fused, work-stealing ranges + static depth-3 cp.async pipeline:
//  Work unit = range of 4 chunks (128 rows each), always within one batch.
//  2048 ranges, grabbed via one global atomic counter (one-range lookahead
//  hides ATOMG latency). Fast blocks steal what slow blocks can't take ->
//  per-SM time ~= mean (kills the 1.68x max-over-SMs imbalance that pinned
//  DRAM at ~34% across all static schedules).
//  Per range: accumulate 4 chunks in registers, one block-reduce, write slot
//  [acc][range] (deferred one iteration so no extra barriers). Empty ranges
//  (chunks past seq_len) cost 4 cheap predicated iterations, no DRAM.
//  Last block (atomic ticket) finalizes + resets counter/ticket. Deterministic:
//  slot values depend only on (range, data), never on which block ran them.

#define BATCH 128
#define SEQ   8192
#define NT    128
#define CHUNK 128
#define CH10  (CHUNK * 10)          // 1280 floats per tensor per chunk
#define F4PT  (CH10 / 4)            // 320 float4 per tensor per chunk
#define RPB   16                    // ranges per batch (64 chunks / 4)
#define NR    (BATCH * RPB)         // 2048 ranges
#define GRID  1024
#define NACC  20
#define NWARP (NT / 32)

#define IMAGE_WEIGHT 0.0736196319f

__constant__ float c_w[9] = {
    0.0736196319f, 0.09202453988f, 0.1042944785f, 0.1042944785f,
    0.1877300613f, 0.06257668712f, 0.06257668712f, 0.2346625767f,
    0.0782208589f
};

__device__ __align__(16) float g_partials[NACC * NR];  // [acc][range]; zero-init
__device__ unsigned int g_counter;                     // reset by finalizer
__device__ unsigned int g_ticket;                      // reset by finalizer

__device__ __forceinline__ void cp16(uint32_t s, const void* g, bool p)
{
    asm volatile(
        "{ .reg .pred q; setp.ne.u32 q, %2, 0;"
        "  @q cp.async.cg.shared.global [%0], [%1], 16; }"
        :: "r"(s), "l"(g), "r"((int)p));
}

__global__ __launch_bounds__(NT, 6)
void rsna_fused_kernel(const float* __restrict__ pred,
                       const float* __restrict__ label,
                       const int*   __restrict__ seq_lens,
                       float* __restrict__ out)
{
    const int tid = threadIdx.x;

    __shared__ __align__(16) float s_pred[3][CH10];
    __shared__ __align__(16) float s_lab [3][CH10];
    __shared__ int   s_sl[BATCH];
    __shared__ int   sh_r[4];                 // grabbed range ids (ring)
    __shared__ float s_red[NWARP * NACC];

    s_sl[tid] = __ldg(&seq_lens[tid]);
    if (tid == 0) sh_r[0] = (int)atomicAdd(&g_counter, 1u);
    __syncthreads();

    float acc[NACC];
#pragma unroll
    for (int a = 0; a < NACC; a++) acc[a] = 0.0f;

    // prefetch chunk-stream index i; range = sh_r[(i>>2)&3], chunk-in-batch =
    // (range&15)*4 + (i&3). Always commits one group (static wait counts).
    auto prefetch = [&](int i) {
        const int  r   = sh_r[(i >> 2) & 3];
        const bool on  = (r < NR);
        const int  b   = on ? (r >> 4) : 0;
        const int  cw  = ((r & 15) << 2) + (i & 3);
        const int  lim = on ? (s_sl[b] - cw * CHUNK) * 10 : 0;
        const int  buf = i % 3;
        const float4* pg = (const float4*)pred  + (size_t)b * (SEQ * 10 / 4) + cw * F4PT;
        const float4* lg = (const float4*)label + (size_t)b * (SEQ * 10 / 4) + cw * F4PT;
        const uint32_t sp = (uint32_t)__cvta_generic_to_shared(&s_pred[buf][0]);
        const uint32_t sy = (uint32_t)__cvta_generic_to_shared(&s_lab [buf][0]);
#pragma unroll
        for (int j = 0; j < 5; j++) {          // 640 float4 over 128 threads
            const int idx = tid + j * NT;
            if (idx < F4PT) {
                cp16(sp + idx * 16, pg + idx, (idx * 4) < lim);
            } else {
                const int i2 = idx - F4PT;
                cp16(sy + i2 * 16, lg + i2, (i2 * 4) < lim);
            }
        }
        asm volatile("cp.async.commit_group;");
    };

    prefetch(0);
    prefetch(1);

    int r_cur = 0, c0 = 0, sl_cur = 0, prev_r = -1;

    for (int i = 0; ; i++) {
        const int w = i & 3, q = i >> 2;

        if (w == 0) {
            r_cur = sh_r[q & 3];               // written >=1 sync ago
            if (r_cur >= NR) break;
            const int b = r_cur >> 4;
            c0     = (r_cur & 15) << 2;
            sl_cur = s_sl[b];
        }
        if (w == 1 && tid == 0)                // one-range lookahead grab
            sh_r[(q + 1) & 3] = (int)atomicAdd(&g_counter, 1u);

        asm volatile("cp.async.wait_group 1;");  // chunk i resident
        __syncthreads();                          // + sh_r / s_red visibility

        if (w == 0) {
            if (prev_r >= 0 && tid < NACC)        // deferred flush of prev range
                g_partials[tid * NR + prev_r] =
                    s_red[tid] + s_red[NACC + tid] +
                    s_red[2 * NACC + tid] + s_red[3 * NACC + tid];
#pragma unroll
            for (int a = 0; a < NACC; a++) acc[a] = 0.0f;
        }

        prefetch(i + 2);                          // buffer (i+2)%3 free since top sync

        const int row = (c0 + w) * CHUNK + tid;
        if (row < sl_cur) {
            const int buf = i % 3;
            const float2* pr = (const float2*)&s_pred[buf][tid * 10];
            const float2* lr = (const float2*)&s_lab [buf][tid * 10];
            float2 p0 = pr[0], p1 = pr[1], p2 = pr[2], p3 = pr[3], p4 = pr[4];
            float2 l0 = lr[0], l1 = lr[1], l2 = lr[2], l3 = lr[3], l4 = lr[4];

            acc[0] += p0.y; acc[1] += p1.x; acc[2] += p1.y; acc[3] += p2.x;
            acc[4] += p2.y; acc[5] += p3.x; acc[6] += p3.y; acc[7] += p4.x;
            acc[8] += p4.y;

            acc[9]  += l0.y; acc[10] += l1.x; acc[11] += l1.y; acc[12] += l2.x;
            acc[13] += l2.y; acc[14] += l3.x; acc[15] += l3.y; acc[16] += l4.x;
            acc[17] += l4.y;

            const float p0v = p0.x, y0v = l0.x;
            acc[18] += y0v;
            acc[19] += -(y0v * __logf(p0v) + (1.0f - y0v) * __logf(1.0f - p0v));
        }

        if (w == 3) {                             // end of range: reduce to s_red
#pragma unroll
            for (int a = 0; a < NACC; a++) {
#pragma unroll
                for (int off = 16; off > 0; off >>= 1)
                    acc[a] += __shfl_xor_sync(0xFFFFFFFFu, acc[a], off);
            }
            if ((tid & 31) == 0) {
#pragma unroll
                for (int a = 0; a < NACC; a++)
                    s_red[(tid >> 5) * NACC + a] = acc[a];
            }
            prev_r = r_cur;                       // written out next iteration
        }
    }

    // epilogue: flush the final range, drain dummy groups
    __syncthreads();
    if (prev_r >= 0 && tid < NACC)
        g_partials[tid * NR + prev_r] =
            s_red[tid] + s_red[NACC + tid] +
            s_red[2 * NACC + tid] + s_red[3 * NACC + tid];
    asm volatile("cp.async.wait_group 0;");

    // ---- ticket: last finished block finalizes ----
    __shared__ int s_last;
    __threadfence();
    __syncthreads();
    if (tid == 0) {
        unsigned int t = atomicAdd(&g_ticket, 1u);
        s_last = (t == (unsigned int)(GRID - 1)) ? 1 : 0;
    }
    __syncthreads();
    if (!s_last) return;

    if (tid == 0) { g_ticket = 0; g_counter = 0; }   // reset for graph replay
    __threadfence();

    // ---- finalize: thread b (<128) handles batch b (ranges 16b..16b+15) ----
    float num = 0.0f, wsum = 0.0f;
    if (tid < BATCH) {
        const float4* gp = (const float4*)g_partials;
        float a[NACC];
#pragma unroll
        for (int k = 0; k < NACC; k++) {
            float s = 0.0f;
#pragma unroll
            for (int j = 0; j < RPB / 4; j++) {       // 4 x float4 = 16 ranges
                float4 v = gp[k * (NR / 4) + tid * (RPB / 4) + j];
                s += ((v.x + v.y) + (v.z + v.w));
            }
            a[k] = s;
        }

        const float len = (float)__ldg(&seq_lens[tid]);
        const float inv = 1.0f / len;

        float exam = 0.0f;
#pragma unroll
        for (int c = 0; c < 9; c++) {
            const float pm = a[c]     * inv;
            const float ym = a[9 + c] * inv;
            exam += c_w[c] * (-(ym * __logf(pm) + (1.0f - ym) * __logf(1.0f - pm)));
        }

        const float y0m = a[18] * inv;
        const float iw  = IMAGE_WEIGHT * y0m;
        num  = exam + a[19] * iw;
        wsum = iw * len;
    }

#pragma unroll
    for (int off = 16; off > 0; off >>= 1) {
        num  += __shfl_xor_sync(0xFFFFFFFFu, num,  off);
        wsum += __shfl_xor_sync(0xFFFFFFFFu, wsum, off);
    }
    __shared__ float s_num[NWARP], s_ws[NWARP];
    const int wid = tid >> 5, lane = tid & 31;
    if (lane == 0) { s_num[wid] = num; s_ws[wid] = wsum; }
    __syncthreads();
    if (tid == 0) {
        float n = 0.0f, w = 0.0f;
#pragma unroll
        for (int i = 0; i < NWARP; i++) { n += s_num[i]; w += s_ws[i]; }
        float sumw = 0.0f;
#pragma unroll
        for (int c = 0; c < 9; c++) sumw += c_w[c];
        out[0] = n / ((float)BATCH * sumw + w);
    }
}

extern "C" void kernel_launch(void* const* d_in, const int* in_sizes, int n_in,
                              void* d_out, int out_size)
{
    const float* pred  = (const float*)d_in[0];
    const float* label = (const float*)d_in[1];
    const int*   slens = (const int*)d_in[2];
    float* out = (float*)d_out;

    rsna_fused_kernel<<<GRID, NT>>>(pred, label, slens, out);
}